// round 12
// baseline (speedup 1.0000x reference)
#include <cuda_runtime.h>
#include <cuda_fp16.h>
#include <math.h>

#define BB  8
#define TT  4096
#define CC  1024
#define HSX 64
#define NKP 2048
// 1/sqrt(C) * log2(e): softmax runs in exp2 domain
#define QSCALE 0.0450842201f
#define SPLITS 4
#define ONES_H2 0x3C003C00u

// ---------------- scratch ----------------------------------------------------
__device__ int    g_keep[NKP];
__device__ __half g_Wh[192 * CC];
__device__ __half g_Kh[(size_t)BB * TT * HSX];
__device__ __half g_Vt[(size_t)BB * HSX * TT];
__device__ __half g_Qh[(size_t)BB * TT * HSX];
__device__ float  g_Op[(size_t)BB * 32 * SPLITS * 64 * 64];
__device__ float  g_ml[(size_t)BB * 32 * SPLITS * 2 * 64];

// ---------------- helpers -----------------------------------------------------
__device__ __forceinline__ unsigned h2(float lo, float hi) {
    unsigned r;
    asm("cvt.rn.f16x2.f32 %0, %1, %2;" : "=r"(r) : "f"(hi), "f"(lo));
    return r;
}
__device__ __forceinline__ float ex2(float x) {
    float r; asm("ex2.approx.f32 %0, %1;" : "=f"(r) : "f"(x)); return r;
}
__device__ __forceinline__ unsigned ex2h2(unsigned x) {
    unsigned r; asm("ex2.approx.f16x2 %0, %1;" : "=r"(r) : "r"(x)); return r;
}
__device__ __forceinline__ void mma_f16(float d[4], const unsigned a[4],
                                        const unsigned b0, const unsigned b1) {
    asm("mma.sync.aligned.m16n8k16.row.col.f32.f16.f16.f32 "
        "{%0,%1,%2,%3}, {%4,%5,%6,%7}, {%8,%9}, {%0,%1,%2,%3};"
        : "+f"(d[0]), "+f"(d[1]), "+f"(d[2]), "+f"(d[3])
        : "r"(a[0]), "r"(a[1]), "r"(a[2]), "r"(a[3]), "r"(b0), "r"(b1));
}
__device__ __forceinline__ void ldsm4(unsigned& r0, unsigned& r1,
                                      unsigned& r2, unsigned& r3, unsigned a) {
    asm volatile("ldmatrix.sync.aligned.m8n8.x4.shared.b16 {%0,%1,%2,%3}, [%4];"
                 : "=r"(r0), "=r"(r1), "=r"(r2), "=r"(r3) : "r"(a));
}
__device__ __forceinline__ void cpa16(unsigned dst_smem, const void* src) {
    asm volatile("cp.async.ca.shared.global [%0], [%1], 16;"
                 :: "r"(dst_smem), "l"(src));
}
__device__ __forceinline__ unsigned s2u(const void* p) {
    unsigned r;
    asm("{ .reg .u64 t; cvta.to.shared.u64 t, %1; cvt.u32.u64 %0, t; }"
        : "=r"(r) : "l"(p));
    return r;
}

// ---------------- keep indices ------------------------------------------------
__global__ void keep_kernel() {
    int i = blockIdx.x * blockDim.x + threadIdx.x;
    if (i >= NKP) return;
    const int a = (TT + 3) / 4;
    int x = NKP - 1 - i;
    int v;
    if (x < a) v = TT - 1 - x;
    else {
        int k = x - a;
        double t = (3.0 / (double)a) * (double)k * (double)k + (double)a;
        v = TT - 1 - (int)ceil(t);
    }
    g_keep[i] = v;
}

// ---------------- W pre-convert -----------------------------------------------
__global__ __launch_bounds__(256) void convw_kernel(
    const float* __restrict__ Wq, const float* __restrict__ Wk,
    const float* __restrict__ Wv)
{
    int i = blockIdx.x * 256 + threadIdx.x;
    if (i >= 192 * CC / 2) return;
    int idx = i * 2;
    int r = idx >> 10, c = idx & (CC - 1);
    const float* W = (r < 64) ? (Wq + (size_t)r * CC)
                   : (r < 128) ? (Wk + (size_t)(r - 64) * CC)
                               : (Wv + (size_t)(r - 128) * CC);
    float2 v = *(const float2*)(W + c);
    ((unsigned*)g_Wh)[i] = h2(v.x, v.y);
}

// ---------------- fused Q,K,V projection: BK=64 stages ------------------------
// 256 threads, 8 warps in 2x4 grid, warp tile 32x48. Dynamic smem:
//   Xs[64][36]  (u32) at 0, Ws[2][192][36] after it.  64512 bytes total.
#define XS_U    (64 * 36)
#define WBUF_U  (192 * 36)
#define PSMEM_B ((XS_U + 2 * WBUF_U) * 4)

__global__ __launch_bounds__(256, 2) void proj_kernel(
    const float* __restrict__ x,
    const float* __restrict__ bq, const float* __restrict__ bk,
    const float* __restrict__ bv)
{
    extern __shared__ unsigned psm[];
    unsigned* Xs = psm;
    const int tid = threadIdx.x, lane = tid & 31, warp = tid >> 5;
    const int g = lane >> 2, tg = lane & 3;
    const int wm = warp >> 2, wn = warp & 3;
    const size_t m0 = (size_t)blockIdx.x * 64;
    const int bidx = blockIdx.x >> 6;
    const int t_in = (int)(m0 % TT);

    const unsigned xsb = s2u(psm);
    const unsigned wsb = xsb + XS_U * 4;
    const int lrow_m = (lane & 7) + ((lane >> 4) << 3);
    const int lcol_m = ((lane >> 3) & 1) * 4;
    const int arow_m = lane & 15;
    const int acol_m = (lane >> 4) << 2;

    float acc[2][6][4];
#pragma unroll
    for (int i = 0; i < 2; i++)
#pragma unroll
        for (int j = 0; j < 6; j++)
#pragma unroll
            for (int q = 0; q < 4; q++) acc[i][j][q] = 0.f;

    // X staging: row = tid>>2 (0..63), 16-half chunk = tid&3
    const int xrow = tid >> 2, xc16 = (tid & 3) * 16, xcu = (tid & 3) * 8;
    const float* xrow_p = x + (m0 + xrow) * CC + xc16;

    float4 xv[4], xn[4];
#pragma unroll
    for (int i = 0; i < 4; i++) xv[i] = *(const float4*)(xrow_p + i * 4);

    // prologue: W stage 0 into buffer 0
#pragma unroll
    for (int s = 0; s < 6; s++) {
        int idx = tid + s * 256;
        int r = idx >> 3, c = idx & 7;
        cpa16(wsb + (r * 36 + c * 4) * 4, g_Wh + (size_t)r * CC + c * 8);
    }
    asm volatile("cp.async.commit_group;");

    int pos = 0;
    for (int k0 = 0; k0 < CC; k0 += 64, pos ^= 1) {
        __syncthreads();               // prior stage's ldsm done
        // ---- STS X (16 halfs per thread)
        {
            uint4 u0 = {h2(xv[0].x, xv[0].y), h2(xv[0].z, xv[0].w),
                        h2(xv[1].x, xv[1].y), h2(xv[1].z, xv[1].w)};
            uint4 u1 = {h2(xv[2].x, xv[2].y), h2(xv[2].z, xv[2].w),
                        h2(xv[3].x, xv[3].y), h2(xv[3].z, xv[3].w)};
            *(uint4*)&Xs[xrow * 36 + xcu]     = u0;
            *(uint4*)&Xs[xrow * 36 + xcu + 4] = u1;
        }
        const bool more = (k0 + 64 < CC);
        if (more) {
#pragma unroll
            for (int s = 0; s < 6; s++) {
                int idx = tid + s * 256;
                int r = idx >> 3, c = idx & 7;
                cpa16(wsb + ((pos ^ 1) * WBUF_U + r * 36 + c * 4) * 4,
                      g_Wh + (size_t)r * CC + (k0 + 64) + c * 8);
            }
            asm volatile("cp.async.commit_group;");
#pragma unroll
            for (int i = 0; i < 4; i++)
                xn[i] = *(const float4*)(xrow_p + k0 + 64 + i * 4);
            asm volatile("cp.async.wait_group 1;");
        } else {
            asm volatile("cp.async.wait_group 0;");
        }
        __syncthreads();               // Xs + Ws[pos] visible

        const unsigned wb = wsb + (pos * WBUF_U) * 4;
#pragma unroll
        for (int kc = 0; kc < 4; kc++) {
            const int kk = kc * 8;
            unsigned a[2][4], bf[6][2];
#pragma unroll
            for (int mi = 0; mi < 2; mi++) {
                unsigned ad = xsb +
                    (((wm * 32 + mi * 16 + arow_m) * 36) + kk + acol_m) * 4;
                ldsm4(a[mi][0], a[mi][1], a[mi][2], a[mi][3], ad);
            }
#pragma unroll
            for (int p = 0; p < 3; p++) {
                unsigned ad = wb +
                    (((wn * 48 + p * 16 + lrow_m) * 36) + kk + lcol_m) * 4;
                ldsm4(bf[2 * p][0], bf[2 * p][1],
                      bf[2 * p + 1][0], bf[2 * p + 1][1], ad);
            }
#pragma unroll
            for (int mi = 0; mi < 2; mi++)
#pragma unroll
                for (int ni = 0; ni < 6; ni++)
                    mma_f16(acc[mi][ni], a[mi], bf[ni][0], bf[ni][1]);
        }
        if (more) {
#pragma unroll
            for (int i = 0; i < 4; i++) xv[i] = xn[i];
        }
    }

#pragma unroll
    for (int mi = 0; mi < 2; mi++) {
        size_t row = m0 + wm * 32 + mi * 16 + g;
        int t = t_in + wm * 32 + mi * 16 + g;
#pragma unroll
        for (int ni = 0; ni < 6; ni++) {
            int col = wn * 48 + ni * 8 + 2 * tg;
            if (col < 64) {
                float b0 = bq[col], b1 = bq[col + 1];
                ((unsigned*)g_Qh)[row * 32 + col / 2] =
                    h2((acc[mi][ni][0] + b0) * QSCALE, (acc[mi][ni][1] + b1) * QSCALE);
                ((unsigned*)g_Qh)[(row + 8) * 32 + col / 2] =
                    h2((acc[mi][ni][2] + b0) * QSCALE, (acc[mi][ni][3] + b1) * QSCALE);
            } else if (col < 128) {
                int c = col - 64;
                float b0 = bk[c], b1 = bk[c + 1];
                ((unsigned*)g_Kh)[row * 32 + c / 2] =
                    h2(acc[mi][ni][0] + b0, acc[mi][ni][1] + b1);
                ((unsigned*)g_Kh)[(row + 8) * 32 + c / 2] =
                    h2(acc[mi][ni][2] + b0, acc[mi][ni][3] + b1);
            } else {
                int c = col - 128;
                float b0 = bv[c], b1 = bv[c + 1];
                size_t base0 = ((size_t)bidx * HSX + c) * TT;
                size_t base1 = base0 + TT;
                g_Vt[base0 + t]     = __float2half_rn(acc[mi][ni][0] + b0);
                g_Vt[base1 + t]     = __float2half_rn(acc[mi][ni][1] + b1);
                g_Vt[base0 + t + 8] = __float2half_rn(acc[mi][ni][2] + b0);
                g_Vt[base1 + t + 8] = __float2half_rn(acc[mi][ni][3] + b1);
            }
        }
    }
}

// ---------------- flash attention: pipelined S, 4-buffer ring -----------------
#define BUF_U   4608
#define VS_OFF  2304
#define NBUF    4
#define SMEM_B  (NBUF * BUF_U * 4)

__global__ __launch_bounds__(128, 3) void attn_kernel() {
    extern __shared__ unsigned smu[];
    __shared__ int keep_s[64];

    const int tid = threadIdx.x, lane = tid & 31, warp = tid >> 5;
    const int g = lane >> 2, tg = lane & 3;
    const int b = blockIdx.y;
    const int j = 31 - (blockIdx.x >> 2);
    const int s = blockIdx.x & 3;
    const int q0 = j * 64;
    const int rb = warp * 16;
    const int unit = (b * 32 + j) * SPLITS + s;

    if (tid < 64) keep_s[tid] = g_keep[q0 + tid];
    __syncthreads();
    const int nkt = keep_s[63] / 64 + 1;
    const int csz = (nkt + SPLITS - 1) / SPLITS;
    const int kt0 = s * csz;
    const int kt1 = min(nkt, kt0 + csz);
    const int kqmin = keep_s[rb];
    const int kq0 = keep_s[rb + g], kq1 = keep_s[rb + g + 8];

    if (kt0 >= kt1) {
        if ((lane & 3) == 0) {
            g_ml[(size_t)unit * 128 + rb + g]          = -1e30f;
            g_ml[(size_t)unit * 128 + rb + g + 8]      = -1e30f;
            g_ml[(size_t)unit * 128 + 64 + rb + g]     = 0.f;
            g_ml[(size_t)unit * 128 + 64 + rb + g + 8] = 0.f;
        }
        return;
    }

    const unsigned smem_b = s2u(smu);
    const unsigned moff = (((lane & 7) + ((lane >> 4) << 3)) * 36 +
                           ((lane >> 3) & 1) * 4) * 4;

#pragma unroll
    for (int i = 0; i < 4; i++) {
        int gid = tid + i * 128;
        int r = gid >> 3, gc = gid & 7;
        cpa16(smem_b + (r * 36 + gc * 4) * 4,
              g_Qh + ((size_t)b * TT + keep_s[r]) * HSX + gc * 8);
    }
    asm volatile("cp.async.commit_group;");
    asm volatile("cp.async.wait_group 0;");
    __syncthreads();

    unsigned qf[4][4];
#pragma unroll
    for (int kc = 0; kc < 4; kc++) {
        qf[kc][0] = smu[(rb + g) * 36 + kc * 8 + tg];
        qf[kc][1] = smu[(rb + g + 8) * 36 + kc * 8 + tg];
        qf[kc][2] = smu[(rb + g) * 36 + kc * 8 + tg + 4];
        qf[kc][3] = smu[(rb + g + 8) * 36 + kc * 8 + tg + 4];
    }
    __syncthreads();

    const __half* Kb0 = g_Kh + (size_t)b * TT * HSX;
    const __half* Vb0 = g_Vt + (size_t)b * HSX * TT;

    {
        const __half* Kb = Kb0 + (size_t)kt0 * 64 * HSX;
        const __half* Vb = Vb0 + (size_t)kt0 * 64;
#pragma unroll
        for (int i = 0; i < 4; i++) {
            int gid = tid + i * 128;
            int r = gid >> 3, gc = gid & 7;
            cpa16(smem_b + (r * 36 + gc * 4) * 4,          Kb + (size_t)r * HSX + gc * 8);
            cpa16(smem_b + (VS_OFF + r * 36 + gc * 4) * 4, Vb + (size_t)r * TT + gc * 8);
        }
        asm volatile("cp.async.commit_group;");
    }
    if (kt0 + 1 < kt1) {
        const __half* Kb = Kb0 + (size_t)(kt0 + 1) * 64 * HSX;
        const __half* Vb = Vb0 + (size_t)(kt0 + 1) * 64;
#pragma unroll
        for (int i = 0; i < 4; i++) {
            int gid = tid + i * 128;
            int r = gid >> 3, gc = gid & 7;
            cpa16(smem_b + (BUF_U + r * 36 + gc * 4) * 4,          Kb + (size_t)r * HSX + gc * 8);
            cpa16(smem_b + (BUF_U + VS_OFF + r * 36 + gc * 4) * 4, Vb + (size_t)r * TT + gc * 8);
        }
        asm volatile("cp.async.commit_group;");
        asm volatile("cp.async.wait_group 1;");
    } else {
        asm volatile("cp.async.wait_group 0;");
    }
    __syncthreads();

    float of[8][4];
#pragma unroll
    for (int i = 0; i < 8; i++)
#pragma unroll
        for (int jj = 0; jj < 4; jj++) of[i][jj] = 0.f;
    float m0_ = -1e30f, m1_ = -1e30f, l0 = 0.f, l1 = 0.f;

    float sacc[8][4], saccn[8][4];
#pragma unroll
    for (int i = 0; i < 8; i++)
#pragma unroll
        for (int jj = 0; jj < 4; jj++) sacc[i][jj] = 0.f;
#pragma unroll
    for (int kc = 0; kc < 4; kc++) {
#pragma unroll
        for (int nb = 0; nb < 4; nb++) {
            unsigned b0, b1, b2, b3;
            ldsm4(b0, b1, b2, b3,
                  smem_b + (unsigned)(nb * 16 * 36 + kc * 8) * 4 + moff);
            mma_f16(sacc[2 * nb],     qf[kc], b0, b1);
            mma_f16(sacc[2 * nb + 1], qf[kc], b2, b3);
        }
    }

    for (int kt = kt0; kt < kt1; kt++) {
        const int idx = kt - kt0;
        const bool pf = (kt + 2 < kt1);
        const bool nxt = (kt + 1 < kt1);
        if (pf) {
            const unsigned bo = ((idx + 2) & 3) * BUF_U;
            const __half* Kb = Kb0 + (size_t)(kt + 2) * 64 * HSX;
            const __half* Vb = Vb0 + (size_t)(kt + 2) * 64;
#pragma unroll
            for (int i = 0; i < 4; i++) {
                int gid = tid + i * 128;
                int r = gid >> 3, gc = gid & 7;
                cpa16(smem_b + (bo + r * 36 + gc * 4) * 4,          Kb + (size_t)r * HSX + gc * 8);
                cpa16(smem_b + (bo + VS_OFF + r * 36 + gc * 4) * 4, Vb + (size_t)r * TT + gc * 8);
            }
            asm volatile("cp.async.commit_group;");
            asm volatile("cp.async.wait_group 1;");
        } else {
            asm volatile("cp.async.wait_group 0;");
        }
        __syncthreads();

        if (kt * 64 + 63 > kqmin) {
            const int tcol = kt * 64 + 2 * tg;
#pragma unroll
            for (int ni = 0; ni < 8; ni++) {
                int t = tcol + ni * 8;
                if (t > kq0)     sacc[ni][0] = -1e30f;
                if (t + 1 > kq0) sacc[ni][1] = -1e30f;
                if (t > kq1)     sacc[ni][2] = -1e30f;
                if (t + 1 > kq1) sacc[ni][3] = -1e30f;
            }
        }
        float rmax0 = -1e30f, rmax1 = -1e30f;
#pragma unroll
        for (int ni = 0; ni < 8; ni++) {
            rmax0 = fmaxf(rmax0, fmaxf(sacc[ni][0], sacc[ni][1]));
            rmax1 = fmaxf(rmax1, fmaxf(sacc[ni][2], sacc[ni][3]));
        }
        rmax0 = fmaxf(rmax0, __shfl_xor_sync(0xffffffffu, rmax0, 1));
        rmax0 = fmaxf(rmax0, __shfl_xor_sync(0xffffffffu, rmax0, 2));
        rmax1 = fmaxf(rmax1, __shfl_xor_sync(0xffffffffu, rmax1, 1));
        rmax1 = fmaxf(rmax1, __shfl_xor_sync(0xffffffffu, rmax1, 2));

        if (nxt) {
            const unsigned kn_b = smem_b + (((idx + 1) & 3) * BUF_U) * 4;
#pragma unroll
            for (int i = 0; i < 8; i++)
#pragma unroll
                for (int jj = 0; jj < 4; jj++) saccn[i][jj] = 0.f;
#pragma unroll
            for (int kc = 0; kc < 4; kc++) {
#pragma unroll
                for (int nb = 0; nb < 4; nb++) {
                    unsigned b0, b1, b2, b3;
                    ldsm4(b0, b1, b2, b3,
                          kn_b + (unsigned)(nb * 16 * 36 + kc * 8) * 4 + moff);
                    mma_f16(saccn[2 * nb],     qf[kc], b0, b1);
                    mma_f16(saccn[2 * nb + 1], qf[kc], b2, b3);
                }
            }
        }

        const float mn0 = fmaxf(m0_, rmax0), mn1 = fmaxf(m1_, rmax1);
        const float mb0 = (mn0 == -1e30f) ? 0.f : mn0;
        const float mb1 = (mn1 == -1e30f) ? 0.f : mn1;
        const float al0 = ex2(m0_ - mb0), al1 = ex2(m1_ - mb1);
        m0_ = mn0; m1_ = mn1;

        unsigned pA[8], pB[8];
#pragma unroll
        for (int ni = 0; ni < 8; ni++) {
            pA[ni] = ex2h2(h2(sacc[ni][0] - mb0, sacc[ni][1] - mb0));
            pB[ni] = ex2h2(h2(sacc[ni][2] - mb1, sacc[ni][3] - mb1));
        }
        l0 *= al0; l1 *= al1;
#pragma unroll
        for (int ni = 0; ni < 8; ni++) {
            of[ni][0] *= al0; of[ni][1] *= al0;
            of[ni][2] *= al1; of[ni][3] *= al1;
        }

        const unsigned vs_b = smem_b + ((idx & 3) * BUF_U + VS_OFF) * 4;
        float racc[4] = {0.f, 0.f, 0.f, 0.f};
#pragma unroll
        for (int kb = 0; kb < 4; kb++) {
            unsigned a[4];
            a[0] = pA[2 * kb];
            a[1] = pB[2 * kb];
            a[2] = pA[2 * kb + 1];
            a[3] = pB[2 * kb + 1];
            mma_f16(racc, a, ONES_H2, ONES_H2);
#pragma unroll
            for (int nb = 0; nb < 4; nb++) {
                unsigned b0, b1, b2, b3;
                ldsm4(b0, b1, b2, b3,
                      vs_b + (unsigned)(nb * 16 * 36 + kb * 8) * 4 + moff);
                mma_f16(of[2 * nb],     a, b0, b1);
                mma_f16(of[2 * nb + 1], a, b2, b3);
            }
        }
        l0 += racc[0];
        l1 += racc[2];

        if (nxt) {
#pragma unroll
            for (int i = 0; i < 8; i++)
#pragma unroll
                for (int jj = 0; jj < 4; jj++) sacc[i][jj] = saccn[i][jj];
        }
    }

    const size_t obase = (size_t)unit * 64;
#pragma unroll
    for (int no = 0; no < 8; no++) {
        int c = no * 8 + 2 * tg;
        *(float2*)(g_Op + (obase + rb + g) * 64 + c) =
            make_float2(of[no][0], of[no][1]);
        *(float2*)(g_Op + (obase + rb + 8 + g) * 64 + c) =
            make_float2(of[no][2], of[no][3]);
    }
    if ((lane & 3) == 0) {
        g_ml[(size_t)unit * 128 + rb + g]          = m0_;
        g_ml[(size_t)unit * 128 + rb + g + 8]      = m1_;
        g_ml[(size_t)unit * 128 + 64 + rb + g]     = l0;
        g_ml[(size_t)unit * 128 + 64 + rb + g + 8] = l1;
    }
}

// ---------------- combine ------------------------------------------------------
__global__ __launch_bounds__(1024) void combine_kernel(float* __restrict__ out) {
    const int b = blockIdx.y, j = blockIdx.x;
    const int tid = threadIdx.x;
    const int r = tid >> 4, seg = (tid & 15) * 4;
    const size_t ub = (size_t)(b * 32 + j) * SPLITS;

    float m[SPLITS], l[SPLITS];
    float mstar = -1e30f;
#pragma unroll
    for (int s = 0; s < SPLITS; s++) {
        m[s] = g_ml[(ub + s) * 128 + r];
        l[s] = g_ml[(ub + s) * 128 + 64 + r];
        mstar = fmaxf(mstar, m[s]);
    }
    float c[SPLITS], L = 0.f;
#pragma unroll
    for (int s = 0; s < SPLITS; s++) {
        c[s] = ex2(m[s] - mstar);
        L += l[s] * c[s];
    }
    const float inv = 1.f / L;
#pragma unroll
    for (int s = 0; s < SPLITS; s++) c[s] *= inv;

    float4 a0 = make_float4(0.f, 0.f, 0.f, 0.f);
#pragma unroll
    for (int s = 0; s < SPLITS; s++) {
        float4 v = *(const float4*)(g_Op + ((ub + s) * 64 + r) * 64 + seg);
        a0.x += c[s] * v.x; a0.y += c[s] * v.y;
        a0.z += c[s] * v.z; a0.w += c[s] * v.w;
    }
    const size_t orow = ((size_t)b * NKP + j * 64 + r) * HSX + seg;
    *(float4*)(out + orow) = a0;
}

// ---------------- launcher ------------------------------------------------------
extern "C" void kernel_launch(void* const* d_in, const int* in_sizes, int n_in,
                              void* d_out, int out_size) {
    const float* x  = (const float*)d_in[0];
    const float* Wq = (const float*)d_in[1];
    const float* bq = (const float*)d_in[2];
    const float* Wk = (const float*)d_in[3];
    const float* bk = (const float*)d_in[4];
    const float* Wv = (const float*)d_in[5];
    const float* bv = (const float*)d_in[6];
    float* out = (float*)d_out;

    keep_kernel<<<(NKP + 255) / 256, 256>>>();
    convw_kernel<<<(192 * CC / 2 + 255) / 256, 256>>>(Wq, Wk, Wv);

    cudaFuncSetAttribute(proj_kernel,
                         cudaFuncAttributeMaxDynamicSharedMemorySize, PSMEM_B);
    proj_kernel<<<(BB * TT) / 64, 256, PSMEM_B>>>(x, bq, bk, bv);

    cudaFuncSetAttribute(attn_kernel,
                         cudaFuncAttributeMaxDynamicSharedMemorySize, SMEM_B);
    dim3 grd(32 * SPLITS, BB);
    attn_kernel<<<grd, 128, SMEM_B>>>();

    dim3 gc(32, BB);
    combine_kernel<<<gc, 1024>>>(out);
}

// round 15
// speedup vs baseline: 1.0316x; 1.0316x over previous
#include <cuda_runtime.h>
#include <cuda_fp16.h>
#include <math.h>

#define BB  8
#define TT  4096
#define CC  1024
#define HSX 64
#define NKP 2048
// 1/sqrt(C) * log2(e): softmax runs in exp2 domain
#define QSCALE 0.0450842201f
#define SPLITS 4
#define ONES_H2 0x3C003C00u

// ---------------- scratch ----------------------------------------------------
__device__ int    g_keep[NKP];
__device__ __half g_Wh[192 * CC];
__device__ __half g_Kh[(size_t)BB * TT * HSX];
__device__ __half g_Vt[(size_t)BB * HSX * TT];
__device__ __half g_Qh[(size_t)BB * TT * HSX];
__device__ float  g_Op[(size_t)BB * 32 * SPLITS * 64 * 64];
__device__ float  g_ml[(size_t)BB * 32 * SPLITS * 2 * 64];

// ---------------- helpers -----------------------------------------------------
__device__ __forceinline__ unsigned h2(float lo, float hi) {
    unsigned r;
    asm("cvt.rn.f16x2.f32 %0, %1, %2;" : "=r"(r) : "f"(hi), "f"(lo));
    return r;
}
__device__ __forceinline__ float ex2(float x) {
    float r; asm("ex2.approx.f32 %0, %1;" : "=f"(r) : "f"(x)); return r;
}
__device__ __forceinline__ unsigned ex2h2(unsigned x) {
    unsigned r; asm("ex2.approx.f16x2 %0, %1;" : "=r"(r) : "r"(x)); return r;
}
__device__ __forceinline__ void mma_f16(float d[4], const unsigned a[4],
                                        const unsigned b0, const unsigned b1) {
    asm("mma.sync.aligned.m16n8k16.row.col.f32.f16.f16.f32 "
        "{%0,%1,%2,%3}, {%4,%5,%6,%7}, {%8,%9}, {%0,%1,%2,%3};"
        : "+f"(d[0]), "+f"(d[1]), "+f"(d[2]), "+f"(d[3])
        : "r"(a[0]), "r"(a[1]), "r"(a[2]), "r"(a[3]), "r"(b0), "r"(b1));
}
__device__ __forceinline__ void ldsm4(unsigned& r0, unsigned& r1,
                                      unsigned& r2, unsigned& r3, unsigned a) {
    asm volatile("ldmatrix.sync.aligned.m8n8.x4.shared.b16 {%0,%1,%2,%3}, [%4];"
                 : "=r"(r0), "=r"(r1), "=r"(r2), "=r"(r3) : "r"(a));
}
__device__ __forceinline__ void cpa16(unsigned dst_smem, const void* src) {
    asm volatile("cp.async.ca.shared.global [%0], [%1], 16;"
                 :: "r"(dst_smem), "l"(src));
}
__device__ __forceinline__ unsigned s2u(const void* p) {
    unsigned r;
    asm("{ .reg .u64 t; cvta.to.shared.u64 t, %1; cvt.u32.u64 %0, t; }"
        : "=r"(r) : "l"(p));
    return r;
}

// ---------------- init: keep indices + W fp32->fp16 ---------------------------
__global__ __launch_bounds__(256) void init_kernel(
    const float* __restrict__ Wq, const float* __restrict__ Wk,
    const float* __restrict__ Wv)
{
    int i = blockIdx.x * 256 + threadIdx.x;
    if (i < NKP) {
        const int a = (TT + 3) / 4;
        int x = NKP - 1 - i;
        int v;
        if (x < a) v = TT - 1 - x;
        else {
            int k = x - a;
            double t = (3.0 / (double)a) * (double)k * (double)k + (double)a;
            v = TT - 1 - (int)ceil(t);
        }
        g_keep[i] = v;
    }
    if (i < 192 * CC / 2) {
        int idx = i * 2;
        int r = idx >> 10, c = idx & (CC - 1);
        const float* W = (r < 64) ? (Wq + (size_t)r * CC)
                       : (r < 128) ? (Wk + (size_t)(r - 64) * CC)
                                   : (Wv + (size_t)(r - 128) * CC);
        float2 v = *(const float2*)(W + c);
        ((unsigned*)g_Wh)[i] = h2(v.x, v.y);
    }
}

// ---------------- fused Q,K,V projection --------------------------------------
#define WSTRIDE (192 * 20)

__global__ __launch_bounds__(256, 2) void proj_kernel(
    const float* __restrict__ x,
    const float* __restrict__ bq, const float* __restrict__ bk,
    const float* __restrict__ bv)
{
    __shared__ unsigned Xs[64][20];
    __shared__ unsigned Ws[2][192][20];
    const int tid = threadIdx.x, lane = tid & 31, warp = tid >> 5;
    const int g = lane >> 2, tg = lane & 3;
    const int wm = warp >> 2, wn = warp & 3;
    const size_t m0 = (size_t)blockIdx.x * 64;
    const int bidx = blockIdx.x >> 6;
    const int t_in = (int)(m0 % TT);

    const unsigned xsb = s2u(Xs), wsb = s2u(Ws);
    const int lrow_m = (lane & 7) + ((lane >> 4) << 3);
    const int lcol_m = ((lane >> 3) & 1) * 4;
    const int arow_m = lane & 15;
    const int acol_m = (lane >> 4) << 2;

    float acc[2][6][4];
#pragma unroll
    for (int i = 0; i < 2; i++)
#pragma unroll
        for (int j = 0; j < 6; j++)
#pragma unroll
            for (int q = 0; q < 4; q++) acc[i][j][q] = 0.f;

    const int xr = tid >> 3, xc4 = (tid & 7) * 4, xcu = (tid & 7) * 2;
    const int wr0 = tid >> 2, wch = (tid & 3);

    // X prefetched TWO stages ahead
    float4 xva[2], xvb[2];
#pragma unroll
    for (int s = 0; s < 2; s++) {
        xva[s] = *(const float4*)(x + (m0 + xr + s * 32) * CC + xc4);
        xvb[s] = *(const float4*)(x + (m0 + xr + s * 32) * CC + 32 + xc4);
    }

    // prologue: W stage 0 into Ws[0]
#pragma unroll
    for (int s = 0; s < 3; s++) {
        int r = wr0 + s * 64;
        cpa16(wsb + (r * 20 + wch * 4) * 4, g_Wh + (size_t)r * CC + wch * 8);
    }
    asm volatile("cp.async.commit_group;");

    int pos = 0;
    for (int k0 = 0; k0 < CC; k0 += 32, pos ^= 1) {
        __syncthreads();
#pragma unroll
        for (int s = 0; s < 2; s++) {
            int r = xr + s * 32;
            Xs[r][xcu]     = h2(xva[s].x, xva[s].y);
            Xs[r][xcu + 1] = h2(xva[s].z, xva[s].w);
        }
        const bool more = (k0 + 32 < CC);
        if (more) {
#pragma unroll
            for (int s = 0; s < 3; s++) {
                int r = wr0 + s * 64;
                cpa16(wsb + ((pos ^ 1) * WSTRIDE + r * 20 + wch * 4) * 4,
                      g_Wh + (size_t)r * CC + (k0 + 32) + wch * 8);
            }
            asm volatile("cp.async.commit_group;");
        }
        // slide X window
#pragma unroll
        for (int s = 0; s < 2; s++) xva[s] = xvb[s];
        if (k0 + 64 < CC) {
#pragma unroll
            for (int s = 0; s < 2; s++)
                xvb[s] = *(const float4*)(x + (m0 + xr + s * 32) * CC + k0 + 64 + xc4);
        }
        if (more) asm volatile("cp.async.wait_group 1;");
        else      asm volatile("cp.async.wait_group 0;");
        __syncthreads();

        const unsigned wb = wsb + (pos * WSTRIDE) * 4;
#pragma unroll
        for (int kc = 0; kc < 2; kc++) {
            const int kk = kc * 8;
            unsigned a[2][4], bf[6][2];
#pragma unroll
            for (int mi = 0; mi < 2; mi++) {
                unsigned ad = xsb +
                    (((wm * 32 + mi * 16 + arow_m) * 20) + kk + acol_m) * 4;
                ldsm4(a[mi][0], a[mi][1], a[mi][2], a[mi][3], ad);
            }
#pragma unroll
            for (int p = 0; p < 3; p++) {
                unsigned ad = wb +
                    (((wn * 48 + p * 16 + lrow_m) * 20) + kk + lcol_m) * 4;
                ldsm4(bf[2 * p][0], bf[2 * p][1],
                      bf[2 * p + 1][0], bf[2 * p + 1][1], ad);
            }
#pragma unroll
            for (int mi = 0; mi < 2; mi++)
#pragma unroll
                for (int ni = 0; ni < 6; ni++)
                    mma_f16(acc[mi][ni], a[mi], bf[ni][0], bf[ni][1]);
        }
    }

#pragma unroll
    for (int mi = 0; mi < 2; mi++) {
        size_t row = m0 + wm * 32 + mi * 16 + g;
        int t = t_in + wm * 32 + mi * 16 + g;
#pragma unroll
        for (int ni = 0; ni < 6; ni++) {
            int col = wn * 48 + ni * 8 + 2 * tg;
            if (col < 64) {
                float b0 = bq[col], b1 = bq[col + 1];
                ((unsigned*)g_Qh)[row * 32 + col / 2] =
                    h2((acc[mi][ni][0] + b0) * QSCALE, (acc[mi][ni][1] + b1) * QSCALE);
                ((unsigned*)g_Qh)[(row + 8) * 32 + col / 2] =
                    h2((acc[mi][ni][2] + b0) * QSCALE, (acc[mi][ni][3] + b1) * QSCALE);
            } else if (col < 128) {
                int c = col - 64;
                float b0 = bk[c], b1 = bk[c + 1];
                ((unsigned*)g_Kh)[row * 32 + c / 2] =
                    h2(acc[mi][ni][0] + b0, acc[mi][ni][1] + b1);
                ((unsigned*)g_Kh)[(row + 8) * 32 + c / 2] =
                    h2(acc[mi][ni][2] + b0, acc[mi][ni][3] + b1);
            } else {
                int c = col - 128;
                float b0 = bv[c], b1 = bv[c + 1];
                size_t base0 = ((size_t)bidx * HSX + c) * TT;
                size_t base1 = base0 + TT;
                g_Vt[base0 + t]     = __float2half_rn(acc[mi][ni][0] + b0);
                g_Vt[base1 + t]     = __float2half_rn(acc[mi][ni][1] + b1);
                g_Vt[base0 + t + 8] = __float2half_rn(acc[mi][ni][2] + b0);
                g_Vt[base1 + t + 8] = __float2half_rn(acc[mi][ni][3] + b1);
            }
        }
    }
}

// ---------------- flash attention: pipelined S, 4-buffer ring, warp skip ------
#define BUF_U   4608
#define VS_OFF  2304
#define NBUF    4
#define SMEM_B  (NBUF * BUF_U * 4)

__global__ __launch_bounds__(128, 3) void attn_kernel() {
    extern __shared__ unsigned smu[];
    __shared__ int keep_s[64];

    const int tid = threadIdx.x, lane = tid & 31, warp = tid >> 5;
    const int g = lane >> 2, tg = lane & 3;
    const int b = blockIdx.y;
    const int j = 31 - (blockIdx.x >> 2);
    const int s = blockIdx.x & 3;
    const int q0 = j * 64;
    const int rb = warp * 16;
    const int unit = (b * 32 + j) * SPLITS + s;

    if (tid < 64) keep_s[tid] = g_keep[q0 + tid];
    __syncthreads();
    const int nkt = keep_s[63] / 64 + 1;
    const int csz = (nkt + SPLITS - 1) / SPLITS;
    const int kt0 = s * csz;
    const int kt1 = min(nkt, kt0 + csz);
    const int kqmin = keep_s[rb];
    const int kqmaxw = keep_s[rb + 15];     // warp's max keep (ascending)
    const int kq0 = keep_s[rb + g], kq1 = keep_s[rb + g + 8];

    if (kt0 >= kt1) {
        if ((lane & 3) == 0) {
            g_ml[(size_t)unit * 128 + rb + g]          = -1e30f;
            g_ml[(size_t)unit * 128 + rb + g + 8]      = -1e30f;
            g_ml[(size_t)unit * 128 + 64 + rb + g]     = 0.f;
            g_ml[(size_t)unit * 128 + 64 + rb + g + 8] = 0.f;
        }
        return;
    }

    const unsigned smem_b = s2u(smu);
    const unsigned moff = (((lane & 7) + ((lane >> 4) << 3)) * 36 +
                           ((lane >> 3) & 1) * 4) * 4;

#pragma unroll
    for (int i = 0; i < 4; i++) {
        int gid = tid + i * 128;
        int r = gid >> 3, gc = gid & 7;
        cpa16(smem_b + (r * 36 + gc * 4) * 4,
              g_Qh + ((size_t)b * TT + keep_s[r]) * HSX + gc * 8);
    }
    asm volatile("cp.async.commit_group;");
    asm volatile("cp.async.wait_group 0;");
    __syncthreads();

    unsigned qf[4][4];
#pragma unroll
    for (int kc = 0; kc < 4; kc++) {
        qf[kc][0] = smu[(rb + g) * 36 + kc * 8 + tg];
        qf[kc][1] = smu[(rb + g + 8) * 36 + kc * 8 + tg];
        qf[kc][2] = smu[(rb + g) * 36 + kc * 8 + tg + 4];
        qf[kc][3] = smu[(rb + g + 8) * 36 + kc * 8 + tg + 4];
    }
    __syncthreads();

    const __half* Kb0 = g_Kh + (size_t)b * TT * HSX;
    const __half* Vb0 = g_Vt + (size_t)b * HSX * TT;

    {
        const __half* Kb = Kb0 + (size_t)kt0 * 64 * HSX;
        const __half* Vb = Vb0 + (size_t)kt0 * 64;
#pragma unroll
        for (int i = 0; i < 4; i++) {
            int gid = tid + i * 128;
            int r = gid >> 3, gc = gid & 7;
            cpa16(smem_b + (r * 36 + gc * 4) * 4,          Kb + (size_t)r * HSX + gc * 8);
            cpa16(smem_b + (VS_OFF + r * 36 + gc * 4) * 4, Vb + (size_t)r * TT + gc * 8);
        }
        asm volatile("cp.async.commit_group;");
    }
    if (kt0 + 1 < kt1) {
        const __half* Kb = Kb0 + (size_t)(kt0 + 1) * 64 * HSX;
        const __half* Vb = Vb0 + (size_t)(kt0 + 1) * 64;
#pragma unroll
        for (int i = 0; i < 4; i++) {
            int gid = tid + i * 128;
            int r = gid >> 3, gc = gid & 7;
            cpa16(smem_b + (BUF_U + r * 36 + gc * 4) * 4,          Kb + (size_t)r * HSX + gc * 8);
            cpa16(smem_b + (BUF_U + VS_OFF + r * 36 + gc * 4) * 4, Vb + (size_t)r * TT + gc * 8);
        }
        asm volatile("cp.async.commit_group;");
        asm volatile("cp.async.wait_group 1;");
    } else {
        asm volatile("cp.async.wait_group 0;");
    }
    __syncthreads();

    float of[8][4];
#pragma unroll
    for (int i = 0; i < 8; i++)
#pragma unroll
        for (int jj = 0; jj < 4; jj++) of[i][jj] = 0.f;
    float m0_ = -1e30f, m1_ = -1e30f, l0 = 0.f, l1 = 0.f;

    float sacc[8][4], saccn[8][4];
#pragma unroll
    for (int i = 0; i < 8; i++)
#pragma unroll
        for (int jj = 0; jj < 4; jj++) sacc[i][jj] = 0.f;
    if (kt0 * 64 <= kqmaxw) {
#pragma unroll
        for (int kc = 0; kc < 4; kc++) {
#pragma unroll
            for (int nb = 0; nb < 4; nb++) {
                unsigned b0, b1, b2, b3;
                ldsm4(b0, b1, b2, b3,
                      smem_b + (unsigned)(nb * 16 * 36 + kc * 8) * 4 + moff);
                mma_f16(sacc[2 * nb],     qf[kc], b0, b1);
                mma_f16(sacc[2 * nb + 1], qf[kc], b2, b3);
            }
        }
    }

    for (int kt = kt0; kt < kt1; kt++) {
        const int idx = kt - kt0;
        const bool pf = (kt + 2 < kt1);
        const bool nxt = (kt + 1 < kt1);
        const bool act = (kt * 64 <= kqmaxw);          // tile has unmasked keys
        if (pf) {
            const unsigned bo = ((idx + 2) & 3) * BUF_U;
            const __half* Kb = Kb0 + (size_t)(kt + 2) * 64 * HSX;
            const __half* Vb = Vb0 + (size_t)(kt + 2) * 64;
#pragma unroll
            for (int i = 0; i < 4; i++) {
                int gid = tid + i * 128;
                int r = gid >> 3, gc = gid & 7;
                cpa16(smem_b + (bo + r * 36 + gc * 4) * 4,          Kb + (size_t)r * HSX + gc * 8);
                cpa16(smem_b + (bo + VS_OFF + r * 36 + gc * 4) * 4, Vb + (size_t)r * TT + gc * 8);
            }
            asm volatile("cp.async.commit_group;");
            asm volatile("cp.async.wait_group 1;");
        } else {
            asm volatile("cp.async.wait_group 0;");
        }
        __syncthreads();

        if (act) {
            if (kt * 64 + 63 > kqmin) {
                const int tcol = kt * 64 + 2 * tg;
#pragma unroll
                for (int ni = 0; ni < 8; ni++) {
                    int t = tcol + ni * 8;
                    if (t > kq0)     sacc[ni][0] = -1e30f;
                    if (t + 1 > kq0) sacc[ni][1] = -1e30f;
                    if (t > kq1)     sacc[ni][2] = -1e30f;
                    if (t + 1 > kq1) sacc[ni][3] = -1e30f;
                }
            }
            float rmax0 = -1e30f, rmax1 = -1e30f;
#pragma unroll
            for (int ni = 0; ni < 8; ni++) {
                rmax0 = fmaxf(rmax0, fmaxf(sacc[ni][0], sacc[ni][1]));
                rmax1 = fmaxf(rmax1, fmaxf(sacc[ni][2], sacc[ni][3]));
            }
            rmax0 = fmaxf(rmax0, __shfl_xor_sync(0xffffffffu, rmax0, 1));
            rmax0 = fmaxf(rmax0, __shfl_xor_sync(0xffffffffu, rmax0, 2));
            rmax1 = fmaxf(rmax1, __shfl_xor_sync(0xffffffffu, rmax1, 1));
            rmax1 = fmaxf(rmax1, __shfl_xor_sync(0xffffffffu, rmax1, 2));

            if (nxt && (kt + 1) * 64 <= kqmaxw) {
                const unsigned kn_b = smem_b + (((idx + 1) & 3) * BUF_U) * 4;
#pragma unroll
                for (int i = 0; i < 8; i++)
#pragma unroll
                    for (int jj = 0; jj < 4; jj++) saccn[i][jj] = 0.f;
#pragma unroll
                for (int kc = 0; kc < 4; kc++) {
#pragma unroll
                    for (int nb = 0; nb < 4; nb++) {
                        unsigned b0, b1, b2, b3;
                        ldsm4(b0, b1, b2, b3,
                              kn_b + (unsigned)(nb * 16 * 36 + kc * 8) * 4 + moff);
                        mma_f16(saccn[2 * nb],     qf[kc], b0, b1);
                        mma_f16(saccn[2 * nb + 1], qf[kc], b2, b3);
                    }
                }
            }

            const float mn0 = fmaxf(m0_, rmax0), mn1 = fmaxf(m1_, rmax1);
            const float mb0 = (mn0 == -1e30f) ? 0.f : mn0;
            const float mb1 = (mn1 == -1e30f) ? 0.f : mn1;
            const float al0 = ex2(m0_ - mb0), al1 = ex2(m1_ - mb1);
            m0_ = mn0; m1_ = mn1;

            unsigned pA[8], pB[8];
#pragma unroll
            for (int ni = 0; ni < 8; ni++) {
                pA[ni] = ex2h2(h2(sacc[ni][0] - mb0, sacc[ni][1] - mb0));
                pB[ni] = ex2h2(h2(sacc[ni][2] - mb1, sacc[ni][3] - mb1));
            }
            l0 *= al0; l1 *= al1;
#pragma unroll
            for (int ni = 0; ni < 8; ni++) {
                of[ni][0] *= al0; of[ni][1] *= al0;
                of[ni][2] *= al1; of[ni][3] *= al1;
            }

            const unsigned vs_b = smem_b + ((idx & 3) * BUF_U + VS_OFF) * 4;
            float racc[4] = {0.f, 0.f, 0.f, 0.f};
#pragma unroll
            for (int kb = 0; kb < 4; kb++) {
                unsigned a[4];
                a[0] = pA[2 * kb];
                a[1] = pB[2 * kb];
                a[2] = pA[2 * kb + 1];
                a[3] = pB[2 * kb + 1];
                mma_f16(racc, a, ONES_H2, ONES_H2);
#pragma unroll
                for (int nb = 0; nb < 4; nb++) {
                    unsigned b0, b1, b2, b3;
                    ldsm4(b0, b1, b2, b3,
                          vs_b + (unsigned)(nb * 16 * 36 + kb * 8) * 4 + moff);
                    mma_f16(of[2 * nb],     a, b0, b1);
                    mma_f16(of[2 * nb + 1], a, b2, b3);
                }
            }
            l0 += racc[0];
            l1 += racc[2];

            if (nxt && (kt + 1) * 64 <= kqmaxw) {
#pragma unroll
                for (int i = 0; i < 8; i++)
#pragma unroll
                    for (int jj = 0; jj < 4; jj++) sacc[i][jj] = saccn[i][jj];
            }
        }
    }

    const size_t obase = (size_t)unit * 64;
#pragma unroll
    for (int no = 0; no < 8; no++) {
        int c = no * 8 + 2 * tg;
        *(float2*)(g_Op + (obase + rb + g) * 64 + c) =
            make_float2(of[no][0], of[no][1]);
        *(float2*)(g_Op + (obase + rb + 8 + g) * 64 + c) =
            make_float2(of[no][2], of[no][3]);
    }
    if ((lane & 3) == 0) {
        g_ml[(size_t)unit * 128 + rb + g]          = m0_;
        g_ml[(size_t)unit * 128 + rb + g + 8]      = m1_;
        g_ml[(size_t)unit * 128 + 64 + rb + g]     = l0;
        g_ml[(size_t)unit * 128 + 64 + rb + g + 8] = l1;
    }
}

// ---------------- combine ------------------------------------------------------
__global__ __launch_bounds__(1024) void combine_kernel(float* __restrict__ out) {
    const int b = blockIdx.y, j = blockIdx.x;
    const int tid = threadIdx.x;
    const int r = tid >> 4, seg = (tid & 15) * 4;
    const size_t ub = (size_t)(b * 32 + j) * SPLITS;

    float m[SPLITS], l[SPLITS];
    float mstar = -1e30f;
#pragma unroll
    for (int s = 0; s < SPLITS; s++) {
        m[s] = g_ml[(ub + s) * 128 + r];
        l[s] = g_ml[(ub + s) * 128 + 64 + r];
        mstar = fmaxf(mstar, m[s]);
    }
    float c[SPLITS], L = 0.f;
#pragma unroll
    for (int s = 0; s < SPLITS; s++) {
        c[s] = ex2(m[s] - mstar);
        L += l[s] * c[s];
    }
    const float inv = 1.f / L;
#pragma unroll
    for (int s = 0; s < SPLITS; s++) c[s] *= inv;

    float4 a0 = make_float4(0.f, 0.f, 0.f, 0.f);
#pragma unroll
    for (int s = 0; s < SPLITS; s++) {
        float4 v = *(const float4*)(g_Op + ((ub + s) * 64 + r) * 64 + seg);
        a0.x += c[s] * v.x; a0.y += c[s] * v.y;
        a0.z += c[s] * v.z; a0.w += c[s] * v.w;
    }
    const size_t orow = ((size_t)b * NKP + j * 64 + r) * HSX + seg;
    *(float4*)(out + orow) = a0;
}

// ---------------- launcher ------------------------------------------------------
extern "C" void kernel_launch(void* const* d_in, const int* in_sizes, int n_in,
                              void* d_out, int out_size) {
    const float* x  = (const float*)d_in[0];
    const float* Wq = (const float*)d_in[1];
    const float* bq = (const float*)d_in[2];
    const float* Wk = (const float*)d_in[3];
    const float* bk = (const float*)d_in[4];
    const float* Wv = (const float*)d_in[5];
    const float* bv = (const float*)d_in[6];
    float* out = (float*)d_out;

    init_kernel<<<(192 * CC / 2 + 255) / 256, 256>>>(Wq, Wk, Wv);
    proj_kernel<<<(BB * TT) / 64, 256>>>(x, bq, bk, bv);

    cudaFuncSetAttribute(attn_kernel,
                         cudaFuncAttributeMaxDynamicSharedMemorySize, SMEM_B);
    dim3 grd(32 * SPLITS, BB);
    attn_kernel<<<grd, 128, SMEM_B>>>();

    dim3 gc(32, BB);
    combine_kernel<<<gc, 1024>>>(out);
}